// round 10
// baseline (speedup 1.0000x reference)
#include <cuda_runtime.h>
#include <cstdint>

// Problem constants (BATCH=4, SEQ=4096, DIM=1024)
#define B 4
#define L 4096
#define D 1024
#define DPB 8                // dims per block
#define TD  4                // dim-pair threads per block (DPB/2)
#define NCH 64               // chunks per segment
#define TPB 256              // TD * NCH
#define CS  16               // timesteps per chunk
#define SEG (NCH * CS)       // 1024 timesteps per segment
#define NSEG (L / SEG)       // 4
#define G 4                  // load-group size

__device__ __forceinline__ float2 cmul(float2 u, float2 v) {
    return make_float2(fmaf(u.x, v.x, -u.y * v.y), fmaf(u.x, v.y, u.y * v.x));
}

__device__ __forceinline__ float2 decay(float r, float im) {
    float mag = sqrtf(fmaf(r, r, im * im));
    float s = __expf(-mag) / mag;
    return make_float2(r * s, im * s);
}

__global__ void __launch_bounds__(TPB)
spiral_seg(const float* __restrict__ x,
           const float* __restrict__ pr, const float* __restrict__ pi,
           const float* __restrict__ ir, const float* __restrict__ ii,
           const float* __restrict__ lr, const float* __restrict__ li,
           float* __restrict__ out)
{
    const int dgrp    = blockIdx.x;              // 0..127
    const int b       = blockIdx.y;              // 0..3
    const int dim_id  = threadIdx.x & (TD - 1);  // 0..3
    const int chunk   = threadIdx.x >> 2;        // 0..63
    const int d0      = dgrp * DPB + dim_id * 2;

    __shared__ float4 s_val[NCH][TD];   // chunk scan values (2 complex per entry)
    __shared__ float4 s_pow[6][TD];     // aC^(2^s) for both dims
    __shared__ float4 s_E0[TD];         // carried state across segments

    const float2 a0 = decay(pr[d0],     pi[d0]);
    const float2 a1 = decay(pr[d0 + 1], pi[d0 + 1]);
    const float2 cre = *(const float2*)(ir + d0);
    const float2 cim = *(const float2*)(ii + d0);

    // aC = a^CS (CS=16): 4 squarings
    float2 aC0 = a0, aC1 = a1;
#pragma unroll
    for (int k = 0; k < 4; k++) { aC0 = cmul(aC0, aC0); aC1 = cmul(aC1, aC1); }

    if (chunk == 0) {
        float2 p0 = aC0, p1 = aC1;
#pragma unroll
        for (int s = 0; s < 6; s++) {
            s_pow[s][dim_id] = make_float4(p0.x, p0.y, p1.x, p1.y);
            p0 = cmul(p0, p0); p1 = cmul(p1, p1);
        }
        s_E0[dim_id] = make_float4(lr[b * D + d0], li[b * D + d0],
                                   lr[b * D + d0 + 1], li[b * D + d0 + 1]);
    }
    __syncthreads();

    // w = aC^chunk (for E_c = w*E0 + val[c-1])
    float2 w0 = make_float2(1.f, 0.f), w1 = make_float2(1.f, 0.f);
#pragma unroll
    for (int s = 0; s < 6; s++) {
        if ((chunk >> s) & 1) {
            float4 P = s_pow[s][dim_id];
            w0 = cmul(w0, make_float2(P.x, P.y));
            w1 = cmul(w1, make_float2(P.z, P.w));
        }
    }

#pragma unroll 1
    for (int seg = 0; seg < NSEG; seg++) {
        const size_t base = ((size_t)(b * L + seg * SEG + chunk * CS)) * D + d0;
        const float* xp = x + base;
        float* op = out + base;

        // ---- Phase 1: zero-init local chunk scan ----
        float h0r = 0.f, h0i = 0.f, h1r = 0.f, h1i = 0.f;
#pragma unroll
        for (int g = 0; g < CS / G; g++) {
            float2 xv[G];
#pragma unroll
            for (int k = 0; k < G; k++)
                xv[k] = *(const float2*)(xp + (size_t)(g * G + k) * D);
#pragma unroll
            for (int k = 0; k < G; k++) {
                float n0r = fmaf(a0.x, h0r, fmaf(-a0.y, h0i, cre.x * xv[k].x));
                float n0i = fmaf(a0.x, h0i, fmaf( a0.y, h0r, cim.x * xv[k].x));
                float n1r = fmaf(a1.x, h1r, fmaf(-a1.y, h1i, cre.y * xv[k].y));
                float n1i = fmaf(a1.x, h1i, fmaf( a1.y, h1r, cim.y * xv[k].y));
                h0r = n0r; h0i = n0i; h1r = n1r; h1i = n1i;
            }
        }
        float4 val = make_float4(h0r, h0i, h1r, h1i);
        s_val[chunk][dim_id] = val;

        // ---- Weighted Hillis-Steele over chunks: val[c] = sum_{i<=c} aC^(c-i) T_i ----
#pragma unroll
        for (int s = 0; s < 6; s++) {
            const int step = 1 << s;
            __syncthreads();
            float4 o = (chunk >= step) ? s_val[chunk - step][dim_id]
                                       : make_float4(0.f, 0.f, 0.f, 0.f);
            float4 P = s_pow[s][dim_id];
            __syncthreads();
            val.x = fmaf(P.x, o.x, fmaf(-P.y, o.y, val.x));
            val.y = fmaf(P.x, o.y, fmaf( P.y, o.x, val.y));
            val.z = fmaf(P.z, o.z, fmaf(-P.w, o.w, val.z));
            val.w = fmaf(P.z, o.w, fmaf( P.w, o.z, val.w));
            s_val[chunk][dim_id] = val;
        }
        __syncthreads();

        // ---- E_c = aC^chunk * E0 + val[chunk-1] ----
        float4 E0 = s_E0[dim_id];
        float4 prev = (chunk > 0) ? s_val[chunk - 1][dim_id]
                                  : make_float4(0.f, 0.f, 0.f, 0.f);
        float E0r = fmaf(w0.x, E0.x, fmaf(-w0.y, E0.y, prev.x));
        float E0i = fmaf(w0.x, E0.y, fmaf( w0.y, E0.x, prev.y));
        float E1r = fmaf(w1.x, E0.z, fmaf(-w1.y, E0.w, prev.z));
        float E1i = fmaf(w1.x, E0.w, fmaf( w1.y, E0.z, prev.w));
        __syncthreads();

        if (chunk == NCH - 1) {
            // E0_next = aC^64 * E0 + val[63] (inclusive)
            float4 P5 = s_pow[5][dim_id];                // aC^32
            float2 c640 = cmul(make_float2(P5.x, P5.y), make_float2(P5.x, P5.y));
            float2 c641 = cmul(make_float2(P5.z, P5.w), make_float2(P5.z, P5.w));
            float4 nE;
            nE.x = fmaf(c640.x, E0.x, fmaf(-c640.y, E0.y, val.x));
            nE.y = fmaf(c640.x, E0.y, fmaf( c640.y, E0.x, val.y));
            nE.z = fmaf(c641.x, E0.z, fmaf(-c641.y, E0.w, val.z));
            nE.w = fmaf(c641.x, E0.w, fmaf( c641.y, E0.z, val.w));
            s_E0[dim_id] = nE;
        }

        // ---- Phase 2: exact scan seeded with E_c; x re-read (L2-hot) ----
        h0r = E0r; h0i = E0i; h1r = E1r; h1i = E1i;
#pragma unroll
        for (int g = 0; g < CS / G; g++) {
            float2 xv[G];
#pragma unroll
            for (int k = 0; k < G; k++)
                xv[k] = *(const float2*)(xp + (size_t)(g * G + k) * D);
#pragma unroll
            for (int k = 0; k < G; k++) {
                float n0r = fmaf(a0.x, h0r, fmaf(-a0.y, h0i, cre.x * xv[k].x));
                float n0i = fmaf(a0.x, h0i, fmaf( a0.y, h0r, cim.x * xv[k].x));
                float n1r = fmaf(a1.x, h1r, fmaf(-a1.y, h1i, cre.y * xv[k].y));
                float n1i = fmaf(a1.x, h1i, fmaf( a1.y, h1r, cim.y * xv[k].y));
                h0r = n0r; h0i = n0i; h1r = n1r; h1i = n1i;
                __stcs((float2*)(op + (size_t)(g * G + k) * D), make_float2(h0r, h1r));
            }
        }
        // s_val/s_E0 hazards across segments are covered by the scan-round barriers.
    }
}

extern "C" void kernel_launch(void* const* d_in, const int* in_sizes, int n_in,
                              void* d_out, int out_size) {
    const float* x    = (const float*)d_in[0];
    const float* p_re = (const float*)d_in[1];
    const float* p_im = (const float*)d_in[2];
    const float* i_re = (const float*)d_in[3];
    const float* i_im = (const float*)d_in[4];
    const float* lc_r = (const float*)d_in[5];
    const float* lc_i = (const float*)d_in[6];
    float* out = (float*)d_out;

    dim3 grid(D / DPB, B);   // (128, 4) = 512 blocks x 256 threads
    spiral_seg<<<grid, TPB>>>(x, p_re, p_im, i_re, i_im, lc_r, lc_i, out);
}